// round 13
// baseline (speedup 1.0000x reference)
#include <cuda_runtime.h>
#include <cuda_fp16.h>
#include <mma.h>
#include <cstdint>
#include <math_constants.h>

using namespace nvcuda;

#define NODES 50000
#define D 128
#define C 40
#define EDGES_MAX 1600000
#define SCAN_B 49          // 49 * 1024 = 50176 >= NODES
#define SCAN_PAD 50176
#define XPAD 136           // half ldm padding (272B row stride, conflict-free LDSM)
#define FPAD 68            // float ldm for warp-private epilogue buffer
#define XH_BYTES (128 * XPAD * 2)          // 34816
#define G1_SMEM  (XH_BYTES * 2)            // xh + wh = 69632

// ---------------- scratch (__device__ globals; no allocations) ----------------
__device__ __half  g_W1h[D * D];         // fp16 W1 (converted once per call)
__device__ __half  g_S1h[NODES * D];     // x @ W1   (fp16 storage)
__device__ float   g_H [NODES * D];      // relu(agg + b1)  (fp32)
__device__ __half  g_S2h[NODES * C];     // H @ W2   (fp16 storage)
__device__ int     g_cnt[SCAN_PAD];      // zero at load; scanC re-zeros
__device__ int     g_scanA[SCAN_PAD];
__device__ int     g_bsum[64];
__device__ int     g_rs[NODES + 1];
__device__ int     g_cur[NODES];
__device__ unsigned g_edge[EDGES_MAX];   // packed {w:fp16 <<16 | col:u16}, CSR order

// ================= W1 fp32 -> fp16 (once per call) =================
__global__ void convw_kernel(const float* __restrict__ W1) {
    int i = blockIdx.x * blockDim.x + threadIdx.x;   // half2 units
    if (i < D * D / 2) {
        float2 v = ((const float2*)W1)[i];
        ((__half2*)g_W1h)[i] = __floats2half2_rn(v.x, v.y);
    }
}

// ================= CSR build =================
__global__ void hist_kernel(const int* __restrict__ ei, int E) {
    int t = blockIdx.x * blockDim.x + threadIdx.x;
    int base = t * 8;
    if (base >= E) return;
    if (base + 8 <= E && (E & 7) == 0) {
        int4 a = *(const int4*)(ei + base);
        int4 b = *(const int4*)(ei + base + 4);
        atomicAdd(&g_cnt[a.x], 1); atomicAdd(&g_cnt[a.y], 1);
        atomicAdd(&g_cnt[a.z], 1); atomicAdd(&g_cnt[a.w], 1);
        atomicAdd(&g_cnt[b.x], 1); atomicAdd(&g_cnt[b.y], 1);
        atomicAdd(&g_cnt[b.z], 1); atomicAdd(&g_cnt[b.w], 1);
    } else {
        for (int j = base; j < E && j < base + 8; j++)
            atomicAdd(&g_cnt[ei[j]], 1);
    }
}

// warp-shuffle inclusive scan (2 block syncs total)
__global__ void scanA_kernel() {
    int t = threadIdx.x;
    int i = blockIdx.x * 1024 + t;
    int lane = t & 31, warp = t >> 5;
    int v = g_cnt[i];
#pragma unroll
    for (int off = 1; off < 32; off <<= 1) {
        int u = __shfl_up_sync(0xffffffffu, v, off);
        if (lane >= off) v += u;
    }
    __shared__ int wsum[32];
    if (lane == 31) wsum[warp] = v;
    __syncthreads();
    if (warp == 0) {
        int s = wsum[lane];
#pragma unroll
        for (int off = 1; off < 32; off <<= 1) {
            int u = __shfl_up_sync(0xffffffffu, s, off);
            if (lane >= off) s += u;
        }
        wsum[lane] = s;
    }
    __syncthreads();
    int incl = v + (warp ? wsum[warp - 1] : 0);
    g_scanA[i] = incl;
    if (t == 1023) g_bsum[blockIdx.x] = incl;
}

__global__ void scanC_kernel() {
    __shared__ int s_off;
    __shared__ int warp_s[2];
    int t = threadIdx.x;
    if (t < 64) {
        int v = (t < (int)blockIdx.x) ? g_bsum[t] : 0;
#pragma unroll
        for (int off = 16; off > 0; off >>= 1)
            v += __shfl_down_sync(0xffffffffu, v, off);
        if ((t & 31) == 0) warp_s[t >> 5] = v;
    }
    __syncthreads();
    if (t == 0) s_off = warp_s[0] + warp_s[1];
    __syncthreads();
    int i = blockIdx.x * 1024 + t;
    int incl = g_scanA[i] + s_off;
    int cnt = g_cnt[i];
    g_cnt[i] = 0;                       // reset for next graph replay
    if (i < NODES) {
        int ex = incl - cnt;
        g_rs[i]  = ex;
        g_cur[i] = ex;
        if (i == NODES - 1) g_rs[NODES] = incl;
    }
}

__device__ __forceinline__ unsigned pack_edge(int col, float w) {
    unsigned hw = __half_as_ushort(__float2half_rn(w));
    return (unsigned)col | (hw << 16);
}

__global__ void scatter_kernel(const int* __restrict__ ei,
                               const float* __restrict__ ew, int E) {
    int t = blockIdx.x * blockDim.x + threadIdx.x;
    int base = t * 8;
    if (base >= E) return;
    if (base + 8 <= E && (E & 7) == 0) {
        int4   ra = *(const int4*)(ei + base);
        int4   rb = *(const int4*)(ei + base + 4);
        int4   ca = *(const int4*)(ei + E + base);
        int4   cb = *(const int4*)(ei + E + base + 4);
        float4 wa = *(const float4*)(ew + base);
        float4 wb = *(const float4*)(ew + base + 4);
        int p0 = atomicAdd(&g_cur[ra.x], 1);
        int p1 = atomicAdd(&g_cur[ra.y], 1);
        int p2 = atomicAdd(&g_cur[ra.z], 1);
        int p3 = atomicAdd(&g_cur[ra.w], 1);
        int p4 = atomicAdd(&g_cur[rb.x], 1);
        int p5 = atomicAdd(&g_cur[rb.y], 1);
        int p6 = atomicAdd(&g_cur[rb.z], 1);
        int p7 = atomicAdd(&g_cur[rb.w], 1);
        g_edge[p0] = pack_edge(ca.x, wa.x);
        g_edge[p1] = pack_edge(ca.y, wa.y);
        g_edge[p2] = pack_edge(ca.z, wa.z);
        g_edge[p3] = pack_edge(ca.w, wa.w);
        g_edge[p4] = pack_edge(cb.x, wb.x);
        g_edge[p5] = pack_edge(cb.y, wb.y);
        g_edge[p6] = pack_edge(cb.z, wb.z);
        g_edge[p7] = pack_edge(cb.w, wb.w);
    } else {
        for (int j = base; j < E && j < base + 8; j++) {
            int p = atomicAdd(&g_cur[ei[j]], 1);
            g_edge[p] = pack_edge(ei[E + j], ew[j]);
        }
    }
}

// ====== GEMM1 (wmma): padded smem for BOTH operands, 128 rows/block ===========
__global__ void gemm1_kernel(const float* __restrict__ x, int n) {
    extern __shared__ __align__(16) char smem_raw[];
    __half* xh = (__half*)smem_raw;                  // 128 x XPAD halves
    __half* wh = (__half*)(smem_raw + XH_BYTES);     // 128 x XPAD halves

    int base = blockIdx.x * 128;
    int tid = threadIdx.x;
    int wid = tid >> 5;
    int lane = tid & 31;

    // stage W1h (fp16, global -> padded smem)
    {
        const uint4* Wv = (const uint4*)g_W1h;
        for (int i = tid; i < 128 * 16; i += 256) {
            int rr = i >> 4, cc = i & 15;
            *(uint4*)(wh + rr * XPAD + cc * 8) = Wv[i];
        }
    }
    // load + convert x tile (128 x 128 f32 -> half, padded rows)
    {
        const float4* xv = (const float4*)x;
        for (int i = tid; i < 128 * 32; i += 256) {
            int rr = i >> 5, cc = i & 31;
            int r = base + rr;
            float4 v = (r < n) ? xv[(long long)r * 32 + cc] : make_float4(0, 0, 0, 0);
            __half2 h01 = __floats2half2_rn(v.x, v.y);
            __half2 h23 = __floats2half2_rn(v.z, v.w);
            uint2 pk;
            pk.x = *reinterpret_cast<unsigned*>(&h01);
            pk.y = *reinterpret_cast<unsigned*>(&h23);
            *(uint2*)(xh + rr * XPAD + cc * 4) = pk;
        }
    }
    __syncthreads();

    wmma::fragment<wmma::accumulator, 16, 16, 16, float> acc[8];
#pragma unroll
    for (int c = 0; c < 8; c++) wmma::fill_fragment(acc[c], 0.0f);
#pragma unroll
    for (int k = 0; k < 8; k++) {
        wmma::fragment<wmma::matrix_a, 16, 16, 16, __half, wmma::row_major> a;
        wmma::load_matrix_sync(a, xh + (wid * 16) * XPAD + k * 16, XPAD);
#pragma unroll
        for (int c = 0; c < 8; c++) {
            wmma::fragment<wmma::matrix_b, 16, 16, 16, __half, wmma::row_major> b;
            wmma::load_matrix_sync(b, wh + (k * 16) * XPAD + c * 16, XPAD);
            wmma::mma_sync(acc[c], a, b, acc[c]);
        }
    }
    // epilogue: warp-private reuse of this warp's own 16-row xh slice
    float* fbuf = (float*)(xh + (wid * 16) * XPAD);
    __syncwarp();
#pragma unroll
    for (int h = 0; h < 2; h++) {
#pragma unroll
        for (int c = 0; c < 4; c++)
            wmma::store_matrix_sync(fbuf + c * 16, acc[h * 4 + c],
                                    FPAD, wmma::mem_row_major);
        __syncwarp();
        int row16 = lane >> 1;
        int sub   = lane & 1;
        int r = base + wid * 16 + row16;
        if (r < n) {
            const float* src = fbuf + row16 * FPAD + sub * 32;
            uint2* dst = (uint2*)(g_S1h + (long long)r * D + h * 64 + sub * 32);
#pragma unroll
            for (int j = 0; j < 8; j++) {
                float4 v = *(const float4*)(src + j * 4);
                __half2 h01 = __floats2half2_rn(v.x, v.y);
                __half2 h23 = __floats2half2_rn(v.z, v.w);
                uint2 pk;
                pk.x = *reinterpret_cast<unsigned*>(&h01);
                pk.y = *reinterpret_cast<unsigned*>(&h23);
                dst[j] = pk;
            }
        }
        __syncwarp();
    }
}

// ================= SpMM1 (gather fp16, warp/row, 8-deep MLP) + bias + relu ====
__device__ __forceinline__ void fma4h(float4& acc, float w, uint2 pk) {
    __half2 h01 = *reinterpret_cast<__half2*>(&pk.x);
    __half2 h23 = *reinterpret_cast<__half2*>(&pk.y);
    float2 f01 = __half22float2(h01);
    float2 f23 = __half22float2(h23);
    acc.x = fmaf(w, f01.x, acc.x); acc.y = fmaf(w, f01.y, acc.y);
    acc.z = fmaf(w, f23.x, acc.z); acc.w = fmaf(w, f23.y, acc.w);
}

__device__ __forceinline__ float edge_w(unsigned e) {
    return __half2float(__ushort_as_half((unsigned short)(e >> 16)));
}

__global__ void spmm1_kernel(const float* __restrict__ b1) {
    int w = (blockIdx.x * blockDim.x + threadIdx.x) >> 5;
    int lane = threadIdx.x & 31;
    if (w >= NODES) return;
    int i = g_rs[w], end = g_rs[w + 1];
    float4 acc = make_float4(0, 0, 0, 0);
    const uint2* S1v = (const uint2*)g_S1h;
    for (; i + 8 <= end; i += 8) {
        unsigned e[8];
#pragma unroll
        for (int j = 0; j < 8; j++) e[j] = g_edge[i + j];
        uint2 v[8];
#pragma unroll
        for (int j = 0; j < 8; j++)
            v[j] = S1v[(long long)(e[j] & 0xFFFFu) * 32 + lane];
#pragma unroll
        for (int j = 0; j < 8; j++) fma4h(acc, edge_w(e[j]), v[j]);
    }
    for (; i < end; i++) {
        unsigned e0 = g_edge[i];
        uint2 v0 = S1v[(long long)(e0 & 0xFFFFu) * 32 + lane];
        fma4h(acc, edge_w(e0), v0);
    }
    float4 bv = ((const float4*)b1)[lane];
    acc.x = fmaxf(acc.x + bv.x, 0.0f);
    acc.y = fmaxf(acc.y + bv.y, 0.0f);
    acc.z = fmaxf(acc.z + bv.z, 0.0f);
    acc.w = fmaxf(acc.w + bv.w, 0.0f);
    ((float4*)g_H)[(long long)w * 32 + lane] = acc;
}

// ================= GEMM2: S2h = H @ W2 (32 rows/block, 160 thr) ===============
#define G2_ROWS 32
__global__ void gemm2_kernel(const float* __restrict__ W2, int n) {
    __shared__ float hs[G2_ROWS * D];
    int base = blockIdx.x * G2_ROWS;
    int tid = threadIdx.x;                // 160
    float4* hsv = (float4*)hs;
    const float4* Hv = (const float4*)g_H;
    for (int i = tid; i < G2_ROWS * 32; i += 160) {
        int r = base + (i >> 5);
        hsv[i] = (r < n) ? Hv[(long long)r * 32 + (i & 31)] : make_float4(0, 0, 0, 0);
    }
    __syncthreads();
    int c = tid % C;
    int rg = tid / C;
    float acc[8];
#pragma unroll
    for (int j = 0; j < 8; j++) acc[j] = 0.0f;
#pragma unroll 4
    for (int k = 0; k < D; k++) {
        float wv = W2[k * C + c];
#pragma unroll
        for (int j = 0; j < 8; j++)
            acc[j] = fmaf(hs[(rg * 8 + j) * D + k], wv, acc[j]);
    }
#pragma unroll
    for (int j = 0; j < 8; j++) {
        int r = base + rg * 8 + j;
        if (r < n) g_S2h[(long long)r * C + c] = __float2half_rn(acc[j]);
    }
}

// ============ SpMM2 (gather fp16, 16 lanes/row, 4-deep MLP) + logsoftmax ======
__global__ void spmm2_kernel(const float* __restrict__ b2,
                             float* __restrict__ out) {
    int gt = blockIdx.x * blockDim.x + threadIdx.x;
    int r = gt >> 4;
    int lane16 = gt & 15;
    if (r >= NODES) return;
    bool act = lane16 < 10;
    int i = g_rs[r], end = g_rs[r + 1];
    float4 acc = make_float4(0, 0, 0, 0);
    const uint2* S2v = (const uint2*)g_S2h;
    for (; i + 4 <= end; i += 4) {
        unsigned e[4];
#pragma unroll
        for (int j = 0; j < 4; j++) e[j] = g_edge[i + j];
        if (act) {
            uint2 v[4];
#pragma unroll
            for (int j = 0; j < 4; j++)
                v[j] = S2v[(long long)(e[j] & 0xFFFFu) * 10 + lane16];
#pragma unroll
            for (int j = 0; j < 4; j++) fma4h(acc, edge_w(e[j]), v[j]);
        }
    }
    for (; i < end; i++) {
        unsigned e0 = g_edge[i];
        if (act) {
            uint2 v0 = S2v[(long long)(e0 & 0xFFFFu) * 10 + lane16];
            fma4h(acc, edge_w(e0), v0);
        }
    }
    float4 v = make_float4(0, 0, 0, 0);
    if (act) {
        float4 bv = ((const float4*)b2)[lane16];
        v.x = acc.x + bv.x; v.y = acc.y + bv.y;
        v.z = acc.z + bv.z; v.w = acc.w + bv.w;
    }
    float m = act ? fmaxf(fmaxf(v.x, v.y), fmaxf(v.z, v.w)) : -CUDART_INF_F;
#pragma unroll
    for (int off = 8; off > 0; off >>= 1)
        m = fmaxf(m, __shfl_xor_sync(0xffffffffu, m, off, 16));
    float s = act ? (__expf(v.x - m) + __expf(v.y - m) +
                     __expf(v.z - m) + __expf(v.w - m)) : 0.0f;
#pragma unroll
    for (int off = 8; off > 0; off >>= 1)
        s += __shfl_xor_sync(0xffffffffu, s, off, 16);
    float lse = m + __logf(s);
    if (act) {
        float4 o;
        o.x = v.x - lse; o.y = v.y - lse; o.z = v.z - lse; o.w = v.w - lse;
        ((float4*)out)[(long long)r * 10 + lane16] = o;
    }
}

// =============================================================================
extern "C" void kernel_launch(void* const* d_in, const int* in_sizes, int n_in,
                              void* d_out, int out_size) {
    const float* x  = (const float*)d_in[0];
    const int*   ei = (const int*)d_in[1];    // int32
    const float* ew = (const float*)d_in[2];
    const float* W1 = (const float*)d_in[3];
    const float* b1 = (const float*)d_in[4];
    const float* W2 = (const float*)d_in[5];
    const float* b2 = (const float*)d_in[6];
    float* out = (float*)d_out;

    int n = in_sizes[0] / D;      // 50000
    int E = in_sizes[1] / 2;      // 1.6M

    static cudaStream_t s1;
    static cudaEvent_t evFork, evCSR;
    static bool init_done = false;
    if (!init_done) {
        cudaFuncSetAttribute(gemm1_kernel,
                             cudaFuncAttributeMaxDynamicSharedMemorySize, G1_SMEM);
        cudaStreamCreateWithFlags(&s1, cudaStreamNonBlocking);
        cudaEventCreateWithFlags(&evFork, cudaEventDisableTiming);
        cudaEventCreateWithFlags(&evCSR, cudaEventDisableTiming);
        init_done = true;
    }

    int eThreads = (E + 7) / 8;

    // ---- fork: CSR build on s1, GEMM1 path on main stream ----
    cudaEventRecord(evFork, 0);
    cudaStreamWaitEvent(s1, evFork, 0);

    hist_kernel<<<(eThreads + 255) / 256, 256, 0, s1>>>(ei, E);
    scanA_kernel<<<SCAN_B, 1024, 0, s1>>>();
    scanC_kernel<<<SCAN_B, 1024, 0, s1>>>();
    scatter_kernel<<<(eThreads + 255) / 256, 256, 0, s1>>>(ei, ew, E);
    cudaEventRecord(evCSR, s1);

    convw_kernel<<<(D * D / 2 + 255) / 256, 256>>>(W1);
    gemm1_kernel<<<(n + 127) / 128, 256, G1_SMEM>>>(x, n);

    // ---- join, then layer-1 aggregation onward ----
    cudaStreamWaitEvent(0, evCSR, 0);
    {
        long long threads = (long long)n * 32;
        spmm1_kernel<<<(int)((threads + 255) / 256), 256>>>(b1);
    }
    gemm2_kernel<<<(n + G2_ROWS - 1) / G2_ROWS, 160>>>(W2, n);
    {
        long long threads = (long long)n * 16;
        spmm2_kernel<<<(int)((threads + 255) / 256), 256>>>(b2, out);
    }
}

// round 14
// speedup vs baseline: 1.4271x; 1.4271x over previous
#include <cuda_runtime.h>
#include <cuda_fp16.h>
#include <mma.h>
#include <cstdint>
#include <math_constants.h>

using namespace nvcuda;

#define NODES 50000
#define D 128
#define C 40
#define EDGES_MAX 1600000
#define SCAN_B 49          // 49 * 1024 = 50176 >= NODES
#define SCAN_PAD 50176
#define XPAD 136           // half ldm padding (272B row stride, conflict-free LDSM)
#define FPAD 68            // float ldm for warp-private epilogue buffer
#define XH_BYTES (128 * XPAD * 2)          // 34816
#define G1_SMEM  (XH_BYTES * 2)            // xh + wh = 69632

// ---------------- scratch (__device__ globals; no allocations) ----------------
__device__ __half  g_W1h[D * D];         // fp16 W1 (converted once per call)
__device__ __half  g_S1h[NODES * D];     // x @ W1   (fp16 storage)
__device__ __half  g_Hh [NODES * D];     // relu(agg + b1)  (fp16 storage)
__device__ __half  g_S2h[NODES * C];     // H @ W2   (fp16 storage)
__device__ int     g_cnt[SCAN_PAD];      // zero at load; scanC re-zeros
__device__ int     g_scanA[SCAN_PAD];
__device__ int     g_bsum[64];
__device__ int     g_rs[NODES + 1];
__device__ int     g_cur[NODES];
__device__ unsigned g_edge[EDGES_MAX];   // packed {w:fp16 <<16 | col:u16}, CSR order

// ================= W1 fp32 -> fp16 (once per call) =================
__global__ void convw_kernel(const float* __restrict__ W1) {
    int i = blockIdx.x * blockDim.x + threadIdx.x;   // half2 units
    if (i < D * D / 2) {
        float2 v = ((const float2*)W1)[i];
        ((__half2*)g_W1h)[i] = __floats2half2_rn(v.x, v.y);
    }
}

// ================= CSR build =================
__global__ void hist_kernel(const int* __restrict__ ei, int E) {
    int t = blockIdx.x * blockDim.x + threadIdx.x;
    int base = t * 4;
    if (base >= E) return;
    if (base + 4 <= E && (E & 3) == 0) {
        int4 r4 = *(const int4*)(ei + base);
        atomicAdd(&g_cnt[r4.x], 1);
        atomicAdd(&g_cnt[r4.y], 1);
        atomicAdd(&g_cnt[r4.z], 1);
        atomicAdd(&g_cnt[r4.w], 1);
    } else {
        for (int j = base; j < E && j < base + 4; j++)
            atomicAdd(&g_cnt[ei[j]], 1);
    }
}

// warp-shuffle inclusive scan (2 block syncs total)
__global__ void scanA_kernel() {
    int t = threadIdx.x;
    int i = blockIdx.x * 1024 + t;
    int lane = t & 31, warp = t >> 5;
    int v = g_cnt[i];
#pragma unroll
    for (int off = 1; off < 32; off <<= 1) {
        int u = __shfl_up_sync(0xffffffffu, v, off);
        if (lane >= off) v += u;
    }
    __shared__ int wsum[32];
    if (lane == 31) wsum[warp] = v;
    __syncthreads();
    if (warp == 0) {
        int s = wsum[lane];
#pragma unroll
        for (int off = 1; off < 32; off <<= 1) {
            int u = __shfl_up_sync(0xffffffffu, s, off);
            if (lane >= off) s += u;
        }
        wsum[lane] = s;
    }
    __syncthreads();
    int incl = v + (warp ? wsum[warp - 1] : 0);
    g_scanA[i] = incl;
    if (t == 1023) g_bsum[blockIdx.x] = incl;
}

__global__ void scanC_kernel() {
    __shared__ int s_off;
    __shared__ int warp_s[2];
    int t = threadIdx.x;
    if (t < 64) {
        int v = (t < (int)blockIdx.x) ? g_bsum[t] : 0;
#pragma unroll
        for (int off = 16; off > 0; off >>= 1)
            v += __shfl_down_sync(0xffffffffu, v, off);
        if ((t & 31) == 0) warp_s[t >> 5] = v;
    }
    __syncthreads();
    if (t == 0) s_off = warp_s[0] + warp_s[1];
    __syncthreads();
    int i = blockIdx.x * 1024 + t;
    int incl = g_scanA[i] + s_off;
    int cnt = g_cnt[i];
    g_cnt[i] = 0;                       // reset for next graph replay
    if (i < NODES) {
        int ex = incl - cnt;
        g_rs[i]  = ex;
        g_cur[i] = ex;
        if (i == NODES - 1) g_rs[NODES] = incl;
    }
}

__device__ __forceinline__ unsigned pack_edge(int col, float w) {
    unsigned hw = __half_as_ushort(__float2half_rn(w));
    return (unsigned)col | (hw << 16);
}

__global__ void scatter_kernel(const int* __restrict__ ei,
                               const float* __restrict__ ew, int E) {
    int t = blockIdx.x * blockDim.x + threadIdx.x;
    int base = t * 4;
    if (base >= E) return;
    if (base + 4 <= E && (E & 3) == 0) {
        int4   r4 = *(const int4*)(ei + base);
        int4   c4 = *(const int4*)(ei + E + base);
        float4 w4 = *(const float4*)(ew + base);
        int p0 = atomicAdd(&g_cur[r4.x], 1);
        int p1 = atomicAdd(&g_cur[r4.y], 1);
        int p2 = atomicAdd(&g_cur[r4.z], 1);
        int p3 = atomicAdd(&g_cur[r4.w], 1);
        g_edge[p0] = pack_edge(c4.x, w4.x);
        g_edge[p1] = pack_edge(c4.y, w4.y);
        g_edge[p2] = pack_edge(c4.z, w4.z);
        g_edge[p3] = pack_edge(c4.w, w4.w);
    } else {
        for (int j = base; j < E && j < base + 4; j++) {
            int p = atomicAdd(&g_cur[ei[j]], 1);
            g_edge[p] = pack_edge(ei[E + j], ew[j]);
        }
    }
}

// ====== GEMM1 (wmma): padded smem for BOTH operands, 128 rows/block ===========
__global__ void gemm1_kernel(const float* __restrict__ x, int n) {
    extern __shared__ __align__(16) char smem_raw[];
    __half* xh = (__half*)smem_raw;                  // 128 x XPAD halves
    __half* wh = (__half*)(smem_raw + XH_BYTES);     // 128 x XPAD halves

    int base = blockIdx.x * 128;
    int tid = threadIdx.x;
    int wid = tid >> 5;
    int lane = tid & 31;

    // stage W1h (fp16, global -> padded smem)
    {
        const uint4* Wv = (const uint4*)g_W1h;
        for (int i = tid; i < 128 * 16; i += 256) {
            int rr = i >> 4, cc = i & 15;
            *(uint4*)(wh + rr * XPAD + cc * 8) = Wv[i];
        }
    }
    // load + convert x tile (128 x 128 f32 -> half, padded rows)
    {
        const float4* xv = (const float4*)x;
        for (int i = tid; i < 128 * 32; i += 256) {
            int rr = i >> 5, cc = i & 31;
            int r = base + rr;
            float4 v = (r < n) ? xv[(long long)r * 32 + cc] : make_float4(0, 0, 0, 0);
            __half2 h01 = __floats2half2_rn(v.x, v.y);
            __half2 h23 = __floats2half2_rn(v.z, v.w);
            uint2 pk;
            pk.x = *reinterpret_cast<unsigned*>(&h01);
            pk.y = *reinterpret_cast<unsigned*>(&h23);
            *(uint2*)(xh + rr * XPAD + cc * 4) = pk;
        }
    }
    __syncthreads();

    wmma::fragment<wmma::accumulator, 16, 16, 16, float> acc[8];
#pragma unroll
    for (int c = 0; c < 8; c++) wmma::fill_fragment(acc[c], 0.0f);
#pragma unroll
    for (int k = 0; k < 8; k++) {
        wmma::fragment<wmma::matrix_a, 16, 16, 16, __half, wmma::row_major> a;
        wmma::load_matrix_sync(a, xh + (wid * 16) * XPAD + k * 16, XPAD);
#pragma unroll
        for (int c = 0; c < 8; c++) {
            wmma::fragment<wmma::matrix_b, 16, 16, 16, __half, wmma::row_major> b;
            wmma::load_matrix_sync(b, wh + (k * 16) * XPAD + c * 16, XPAD);
            wmma::mma_sync(acc[c], a, b, acc[c]);
        }
    }
    // epilogue: warp-private reuse of this warp's own 16-row xh slice
    float* fbuf = (float*)(xh + (wid * 16) * XPAD);
    __syncwarp();
#pragma unroll
    for (int h = 0; h < 2; h++) {
#pragma unroll
        for (int c = 0; c < 4; c++)
            wmma::store_matrix_sync(fbuf + c * 16, acc[h * 4 + c],
                                    FPAD, wmma::mem_row_major);
        __syncwarp();
        int row16 = lane >> 1;
        int sub   = lane & 1;
        int r = base + wid * 16 + row16;
        if (r < n) {
            const float* src = fbuf + row16 * FPAD + sub * 32;
            uint2* dst = (uint2*)(g_S1h + (long long)r * D + h * 64 + sub * 32);
#pragma unroll
            for (int j = 0; j < 8; j++) {
                float4 v = *(const float4*)(src + j * 4);
                __half2 h01 = __floats2half2_rn(v.x, v.y);
                __half2 h23 = __floats2half2_rn(v.z, v.w);
                uint2 pk;
                pk.x = *reinterpret_cast<unsigned*>(&h01);
                pk.y = *reinterpret_cast<unsigned*>(&h23);
                dst[j] = pk;
            }
        }
        __syncwarp();
    }
}

// ================= SpMM1 (gather fp16, warp/row, 8-deep MLP) + bias + relu ====
__device__ __forceinline__ void fma4h(float4& acc, float w, uint2 pk) {
    __half2 h01 = *reinterpret_cast<__half2*>(&pk.x);
    __half2 h23 = *reinterpret_cast<__half2*>(&pk.y);
    float2 f01 = __half22float2(h01);
    float2 f23 = __half22float2(h23);
    acc.x = fmaf(w, f01.x, acc.x); acc.y = fmaf(w, f01.y, acc.y);
    acc.z = fmaf(w, f23.x, acc.z); acc.w = fmaf(w, f23.y, acc.w);
}

__device__ __forceinline__ float edge_w(unsigned e) {
    return __half2float(__ushort_as_half((unsigned short)(e >> 16)));
}

__global__ void spmm1_kernel(const float* __restrict__ b1) {
    int w = (blockIdx.x * blockDim.x + threadIdx.x) >> 5;
    int lane = threadIdx.x & 31;
    if (w >= NODES) return;
    int i = g_rs[w], end = g_rs[w + 1];
    float4 acc = make_float4(0, 0, 0, 0);
    const uint2* S1v = (const uint2*)g_S1h;
    for (; i + 8 <= end; i += 8) {
        unsigned e[8];
#pragma unroll
        for (int j = 0; j < 8; j++) e[j] = g_edge[i + j];
        uint2 v[8];
#pragma unroll
        for (int j = 0; j < 8; j++)
            v[j] = S1v[(long long)(e[j] & 0xFFFFu) * 32 + lane];
#pragma unroll
        for (int j = 0; j < 8; j++) fma4h(acc, edge_w(e[j]), v[j]);
    }
    for (; i < end; i++) {
        unsigned e0 = g_edge[i];
        uint2 v0 = S1v[(long long)(e0 & 0xFFFFu) * 32 + lane];
        fma4h(acc, edge_w(e0), v0);
    }
    float4 bv = ((const float4*)b1)[lane];
    acc.x = fmaxf(acc.x + bv.x, 0.0f);
    acc.y = fmaxf(acc.y + bv.y, 0.0f);
    acc.z = fmaxf(acc.z + bv.z, 0.0f);
    acc.w = fmaxf(acc.w + bv.w, 0.0f);
    __half2 h01 = __floats2half2_rn(acc.x, acc.y);
    __half2 h23 = __floats2half2_rn(acc.z, acc.w);
    uint2 pk;
    pk.x = *reinterpret_cast<unsigned*>(&h01);
    pk.y = *reinterpret_cast<unsigned*>(&h23);
    ((uint2*)g_Hh)[(long long)w * 32 + lane] = pk;
}

// ======== GEMM2: S2h = Hh @ W2 (32 rows/block, 160 thr, fp16 H input) =========
#define G2_ROWS 32
__global__ void gemm2_kernel(const float* __restrict__ W2, int n) {
    __shared__ float hs[G2_ROWS * D];    // 16 KB (fp32 after convert)
    int base = blockIdx.x * G2_ROWS;
    int tid = threadIdx.x;                // 160
    const uint2* Hv = (const uint2*)g_Hh; // 4 halves per uint2
    for (int i = tid; i < G2_ROWS * 32; i += 160) {
        int r = base + (i >> 5);
        uint2 pk = (r < n) ? Hv[(long long)r * 32 + (i & 31)] : make_uint2(0, 0);
        __half2 h01 = *reinterpret_cast<__half2*>(&pk.x);
        __half2 h23 = *reinterpret_cast<__half2*>(&pk.y);
        float2 f01 = __half22float2(h01);
        float2 f23 = __half22float2(h23);
        float* dst = hs + (i >> 5) * D + (i & 31) * 4;
        dst[0] = f01.x; dst[1] = f01.y; dst[2] = f23.x; dst[3] = f23.y;
    }
    __syncthreads();
    int c = tid % C;
    int rg = tid / C;
    float acc[8];
#pragma unroll
    for (int j = 0; j < 8; j++) acc[j] = 0.0f;
#pragma unroll 4
    for (int k = 0; k < D; k++) {
        float wv = W2[k * C + c];
#pragma unroll
        for (int j = 0; j < 8; j++)
            acc[j] = fmaf(hs[(rg * 8 + j) * D + k], wv, acc[j]);
    }
#pragma unroll
    for (int j = 0; j < 8; j++) {
        int r = base + rg * 8 + j;
        if (r < n) g_S2h[(long long)r * C + c] = __float2half_rn(acc[j]);
    }
}

// ============ SpMM2 (gather fp16, 16 lanes/row, 4-deep MLP) + logsoftmax ======
__global__ void spmm2_kernel(const float* __restrict__ b2,
                             float* __restrict__ out) {
    int gt = blockIdx.x * blockDim.x + threadIdx.x;
    int r = gt >> 4;
    int lane16 = gt & 15;
    if (r >= NODES) return;
    bool act = lane16 < 10;
    int i = g_rs[r], end = g_rs[r + 1];
    float4 acc = make_float4(0, 0, 0, 0);
    const uint2* S2v = (const uint2*)g_S2h;
    for (; i + 4 <= end; i += 4) {
        unsigned e[4];
#pragma unroll
        for (int j = 0; j < 4; j++) e[j] = g_edge[i + j];
        if (act) {
            uint2 v[4];
#pragma unroll
            for (int j = 0; j < 4; j++)
                v[j] = S2v[(long long)(e[j] & 0xFFFFu) * 10 + lane16];
#pragma unroll
            for (int j = 0; j < 4; j++) fma4h(acc, edge_w(e[j]), v[j]);
        }
    }
    for (; i < end; i++) {
        unsigned e0 = g_edge[i];
        if (act) {
            uint2 v0 = S2v[(long long)(e0 & 0xFFFFu) * 10 + lane16];
            fma4h(acc, edge_w(e0), v0);
        }
    }
    float4 v = make_float4(0, 0, 0, 0);
    if (act) {
        float4 bv = ((const float4*)b2)[lane16];
        v.x = acc.x + bv.x; v.y = acc.y + bv.y;
        v.z = acc.z + bv.z; v.w = acc.w + bv.w;
    }
    float m = act ? fmaxf(fmaxf(v.x, v.y), fmaxf(v.z, v.w)) : -CUDART_INF_F;
#pragma unroll
    for (int off = 8; off > 0; off >>= 1)
        m = fmaxf(m, __shfl_xor_sync(0xffffffffu, m, off, 16));
    float s = act ? (__expf(v.x - m) + __expf(v.y - m) +
                     __expf(v.z - m) + __expf(v.w - m)) : 0.0f;
#pragma unroll
    for (int off = 8; off > 0; off >>= 1)
        s += __shfl_xor_sync(0xffffffffu, s, off, 16);
    float lse = m + __logf(s);
    if (act) {
        float4 o;
        o.x = v.x - lse; o.y = v.y - lse; o.z = v.z - lse; o.w = v.w - lse;
        ((float4*)out)[(long long)r * 10 + lane16] = o;
    }
}

// =============================================================================
extern "C" void kernel_launch(void* const* d_in, const int* in_sizes, int n_in,
                              void* d_out, int out_size) {
    const float* x  = (const float*)d_in[0];
    const int*   ei = (const int*)d_in[1];    // int32
    const float* ew = (const float*)d_in[2];
    const float* W1 = (const float*)d_in[3];
    const float* b1 = (const float*)d_in[4];
    const float* W2 = (const float*)d_in[5];
    const float* b2 = (const float*)d_in[6];
    float* out = (float*)d_out;

    int n = in_sizes[0] / D;      // 50000
    int E = in_sizes[1] / 2;      // 1.6M

    static bool attr_set = false;
    if (!attr_set) {
        cudaFuncSetAttribute(gemm1_kernel,
                             cudaFuncAttributeMaxDynamicSharedMemorySize, G1_SMEM);
        attr_set = true;
    }

    // ---- weight conversion + CSR build (single stream) ----
    convw_kernel<<<(D * D / 2 + 255) / 256, 256>>>(W1);
    int eThreads = (E + 3) / 4;
    hist_kernel<<<(eThreads + 255) / 256, 256>>>(ei, E);
    scanA_kernel<<<SCAN_B, 1024>>>();
    scanC_kernel<<<SCAN_B, 1024>>>();
    scatter_kernel<<<(eThreads + 255) / 256, 256>>>(ei, ew, E);

    // ---- layer 1 ----
    gemm1_kernel<<<(n + 127) / 128, 256, G1_SMEM>>>(x, n);
    {
        long long threads = (long long)n * 32;
        spmm1_kernel<<<(int)((threads + 255) / 256), 256>>>(b1);
    }

    // ---- layer 2 ----
    gemm2_kernel<<<(n + G2_ROWS - 1) / G2_ROWS, 160>>>(W2, n);
    {
        long long threads = (long long)n * 16;
        spmm2_kernel<<<(int)((threads + 255) / 256), 256>>>(b2, out);
    }
}

// round 15
// speedup vs baseline: 1.4973x; 1.0492x over previous
#include <cuda_runtime.h>
#include <cuda_fp16.h>
#include <mma.h>
#include <cstdint>
#include <math_constants.h>

using namespace nvcuda;

#define NODES 50000
#define D 128
#define C 40
#define EDGES_MAX 1600000
#define SCAN_B 49          // 49 * 1024 = 50176 >= NODES
#define SCAN_PAD 50176
#define XPAD 136           // half ldm padding (272B row stride, conflict-free LDSM)
#define FPAD 68            // float ldm for warp-private epilogue buffer
#define XH_BYTES (128 * XPAD * 2)          // 34816
#define G1_SMEM  (XH_BYTES * 2)            // xh + wh = 69632

// ---------------- scratch (__device__ globals; no allocations) ----------------
__device__ __half  g_W1h[D * D];         // fp16 W1 (converted once per call)
__device__ __half  g_S1h[NODES * D];     // x @ W1   (fp16 storage)
__device__ __half  g_Hh [NODES * D];     // relu(agg + b1)  (fp16 storage)
__device__ __half  g_S2h[NODES * C];     // H @ W2   (fp16 storage)
__device__ int     g_cnt[SCAN_PAD];      // zero at load; scanC re-zeros
__device__ int     g_scanA[SCAN_PAD];
__device__ int     g_bsum[64];
__device__ int     g_rs[NODES + 1];
__device__ int     g_cur[NODES];
__device__ unsigned g_edge[EDGES_MAX];   // packed {w:fp16 <<16 | col:u16}, CSR order

// ================= W1 fp32 -> fp16 (once per call) =================
__global__ void convw_kernel(const float* __restrict__ W1) {
    int i = blockIdx.x * blockDim.x + threadIdx.x;   // half2 units
    if (i < D * D / 2) {
        float2 v = ((const float2*)W1)[i];
        ((__half2*)g_W1h)[i] = __floats2half2_rn(v.x, v.y);
    }
}

// ================= CSR build =================
__global__ void hist_kernel(const int* __restrict__ ei, int E) {
    int t = blockIdx.x * blockDim.x + threadIdx.x;
    int base = t * 4;
    if (base >= E) return;
    if (base + 4 <= E && (E & 3) == 0) {
        int4 r4 = *(const int4*)(ei + base);
        atomicAdd(&g_cnt[r4.x], 1);
        atomicAdd(&g_cnt[r4.y], 1);
        atomicAdd(&g_cnt[r4.z], 1);
        atomicAdd(&g_cnt[r4.w], 1);
    } else {
        for (int j = base; j < E && j < base + 4; j++)
            atomicAdd(&g_cnt[ei[j]], 1);
    }
}

// warp-shuffle inclusive scan (2 block syncs total)
__global__ void scanA_kernel() {
    int t = threadIdx.x;
    int i = blockIdx.x * 1024 + t;
    int lane = t & 31, warp = t >> 5;
    int v = g_cnt[i];
#pragma unroll
    for (int off = 1; off < 32; off <<= 1) {
        int u = __shfl_up_sync(0xffffffffu, v, off);
        if (lane >= off) v += u;
    }
    __shared__ int wsum[32];
    if (lane == 31) wsum[warp] = v;
    __syncthreads();
    if (warp == 0) {
        int s = wsum[lane];
#pragma unroll
        for (int off = 1; off < 32; off <<= 1) {
            int u = __shfl_up_sync(0xffffffffu, s, off);
            if (lane >= off) s += u;
        }
        wsum[lane] = s;
    }
    __syncthreads();
    int incl = v + (warp ? wsum[warp - 1] : 0);
    g_scanA[i] = incl;
    if (t == 1023) g_bsum[blockIdx.x] = incl;
}

__global__ void scanC_kernel() {
    __shared__ int s_off;
    __shared__ int warp_s[2];
    int t = threadIdx.x;
    if (t < 64) {
        int v = (t < (int)blockIdx.x) ? g_bsum[t] : 0;
#pragma unroll
        for (int off = 16; off > 0; off >>= 1)
            v += __shfl_down_sync(0xffffffffu, v, off);
        if ((t & 31) == 0) warp_s[t >> 5] = v;
    }
    __syncthreads();
    if (t == 0) s_off = warp_s[0] + warp_s[1];
    __syncthreads();
    int i = blockIdx.x * 1024 + t;
    int incl = g_scanA[i] + s_off;
    int cnt = g_cnt[i];
    g_cnt[i] = 0;                       // reset for next graph replay
    if (i < NODES) {
        int ex = incl - cnt;
        g_rs[i]  = ex;
        g_cur[i] = ex;
        if (i == NODES - 1) g_rs[NODES] = incl;
    }
}

__device__ __forceinline__ unsigned pack_edge(int col, float w) {
    unsigned hw = __half_as_ushort(__float2half_rn(w));
    return (unsigned)col | (hw << 16);
}

__global__ void scatter_kernel(const int* __restrict__ ei,
                               const float* __restrict__ ew, int E) {
    int t = blockIdx.x * blockDim.x + threadIdx.x;
    int base = t * 4;
    if (base >= E) return;
    if (base + 4 <= E && (E & 3) == 0) {
        int4   r4 = *(const int4*)(ei + base);
        int4   c4 = *(const int4*)(ei + E + base);
        float4 w4 = *(const float4*)(ew + base);
        int p0 = atomicAdd(&g_cur[r4.x], 1);
        int p1 = atomicAdd(&g_cur[r4.y], 1);
        int p2 = atomicAdd(&g_cur[r4.z], 1);
        int p3 = atomicAdd(&g_cur[r4.w], 1);
        g_edge[p0] = pack_edge(c4.x, w4.x);
        g_edge[p1] = pack_edge(c4.y, w4.y);
        g_edge[p2] = pack_edge(c4.z, w4.z);
        g_edge[p3] = pack_edge(c4.w, w4.w);
    } else {
        for (int j = base; j < E && j < base + 4; j++) {
            int p = atomicAdd(&g_cur[ei[j]], 1);
            g_edge[p] = pack_edge(ei[E + j], ew[j]);
        }
    }
}

// ====== GEMM1 (wmma): padded smem for BOTH operands, 128 rows/block ===========
__global__ void gemm1_kernel(const float* __restrict__ x, int n) {
    extern __shared__ __align__(16) char smem_raw[];
    __half* xh = (__half*)smem_raw;                  // 128 x XPAD halves
    __half* wh = (__half*)(smem_raw + XH_BYTES);     // 128 x XPAD halves

    int base = blockIdx.x * 128;
    int tid = threadIdx.x;
    int wid = tid >> 5;
    int lane = tid & 31;

    // stage W1h (fp16, global -> padded smem)
    {
        const uint4* Wv = (const uint4*)g_W1h;
        for (int i = tid; i < 128 * 16; i += 256) {
            int rr = i >> 4, cc = i & 15;
            *(uint4*)(wh + rr * XPAD + cc * 8) = Wv[i];
        }
    }
    // load + convert x tile (128 x 128 f32 -> half, padded rows)
    {
        const float4* xv = (const float4*)x;
        for (int i = tid; i < 128 * 32; i += 256) {
            int rr = i >> 5, cc = i & 31;
            int r = base + rr;
            float4 v = (r < n) ? xv[(long long)r * 32 + cc] : make_float4(0, 0, 0, 0);
            __half2 h01 = __floats2half2_rn(v.x, v.y);
            __half2 h23 = __floats2half2_rn(v.z, v.w);
            uint2 pk;
            pk.x = *reinterpret_cast<unsigned*>(&h01);
            pk.y = *reinterpret_cast<unsigned*>(&h23);
            *(uint2*)(xh + rr * XPAD + cc * 4) = pk;
        }
    }
    __syncthreads();

    wmma::fragment<wmma::accumulator, 16, 16, 16, float> acc[8];
#pragma unroll
    for (int c = 0; c < 8; c++) wmma::fill_fragment(acc[c], 0.0f);
#pragma unroll
    for (int k = 0; k < 8; k++) {
        wmma::fragment<wmma::matrix_a, 16, 16, 16, __half, wmma::row_major> a;
        wmma::load_matrix_sync(a, xh + (wid * 16) * XPAD + k * 16, XPAD);
#pragma unroll
        for (int c = 0; c < 8; c++) {
            wmma::fragment<wmma::matrix_b, 16, 16, 16, __half, wmma::row_major> b;
            wmma::load_matrix_sync(b, wh + (k * 16) * XPAD + c * 16, XPAD);
            wmma::mma_sync(acc[c], a, b, acc[c]);
        }
    }
    // epilogue: warp-private reuse of this warp's own 16-row xh slice
    float* fbuf = (float*)(xh + (wid * 16) * XPAD);
    __syncwarp();
#pragma unroll
    for (int h = 0; h < 2; h++) {
#pragma unroll
        for (int c = 0; c < 4; c++)
            wmma::store_matrix_sync(fbuf + c * 16, acc[h * 4 + c],
                                    FPAD, wmma::mem_row_major);
        __syncwarp();
        int row16 = lane >> 1;
        int sub   = lane & 1;
        int r = base + wid * 16 + row16;
        if (r < n) {
            const float* src = fbuf + row16 * FPAD + sub * 32;
            uint2* dst = (uint2*)(g_S1h + (long long)r * D + h * 64 + sub * 32);
#pragma unroll
            for (int j = 0; j < 8; j++) {
                float4 v = *(const float4*)(src + j * 4);
                __half2 h01 = __floats2half2_rn(v.x, v.y);
                __half2 h23 = __floats2half2_rn(v.z, v.w);
                uint2 pk;
                pk.x = *reinterpret_cast<unsigned*>(&h01);
                pk.y = *reinterpret_cast<unsigned*>(&h23);
                dst[j] = pk;
            }
        }
        __syncwarp();
    }
}

// ===== SpMM1 v2: 2 edges per gather instr (uint4/lane), warp/row ==============
__device__ __forceinline__ float edge_w(unsigned e) {
    return __half2float(__ushort_as_half((unsigned short)(e >> 16)));
}

__device__ __forceinline__ void fma8h(float* acc, float w, uint4 pk) {
    __half2 h01 = *reinterpret_cast<__half2*>(&pk.x);
    __half2 h23 = *reinterpret_cast<__half2*>(&pk.y);
    __half2 h45 = *reinterpret_cast<__half2*>(&pk.z);
    __half2 h67 = *reinterpret_cast<__half2*>(&pk.w);
    float2 f01 = __half22float2(h01);
    float2 f23 = __half22float2(h23);
    float2 f45 = __half22float2(h45);
    float2 f67 = __half22float2(h67);
    acc[0] = fmaf(w, f01.x, acc[0]); acc[1] = fmaf(w, f01.y, acc[1]);
    acc[2] = fmaf(w, f23.x, acc[2]); acc[3] = fmaf(w, f23.y, acc[3]);
    acc[4] = fmaf(w, f45.x, acc[4]); acc[5] = fmaf(w, f45.y, acc[5]);
    acc[6] = fmaf(w, f67.x, acc[6]); acc[7] = fmaf(w, f67.y, acc[7]);
}

__global__ void spmm1_kernel(const float* __restrict__ b1) {
    int w = (blockIdx.x * blockDim.x + threadIdx.x) >> 5;
    int lane = threadIdx.x & 31;
    if (w >= NODES) return;
    int pair = lane >> 4;           // which of 2 edges this lane serves
    int sub  = lane & 15;           // 16B chunk within the 256B row
    int i = g_rs[w], end = g_rs[w + 1];
    float acc[8];
#pragma unroll
    for (int k = 0; k < 8; k++) acc[k] = 0.0f;
    const uint4* S1v = (const uint4*)g_S1h;     // row = 16 uint4

    for (; i + 8 <= end; i += 8) {              // 4 pair-iterations = 8 edges
        unsigned e[4];
#pragma unroll
        for (int j = 0; j < 4; j++) e[j] = g_edge[i + 2 * j + pair];
        uint4 v[4];
#pragma unroll
        for (int j = 0; j < 4; j++)
            v[j] = S1v[(long long)(e[j] & 0xFFFFu) * 16 + sub];
#pragma unroll
        for (int j = 0; j < 4; j++) fma8h(acc, edge_w(e[j]), v[j]);
    }
    for (; i < end; i += 2) {
        int idx = i + pair;
        if (idx < end) {
            unsigned e0 = g_edge[idx];
            uint4 v0 = S1v[(long long)(e0 & 0xFFFFu) * 16 + sub];
            fma8h(acc, edge_w(e0), v0);
        }
    }
    // combine the two edge-pairs: lane l += lane l+16
#pragma unroll
    for (int k = 0; k < 8; k++)
        acc[k] += __shfl_down_sync(0xffffffffu, acc[k], 16);

    if (pair == 0) {
        const float4* b1v = (const float4*)b1;  // cols sub*8 .. sub*8+7
        float4 ba = b1v[sub * 2];
        float4 bb = b1v[sub * 2 + 1];
        float r0 = fmaxf(acc[0] + ba.x, 0.0f);
        float r1 = fmaxf(acc[1] + ba.y, 0.0f);
        float r2 = fmaxf(acc[2] + ba.z, 0.0f);
        float r3 = fmaxf(acc[3] + ba.w, 0.0f);
        float r4 = fmaxf(acc[4] + bb.x, 0.0f);
        float r5 = fmaxf(acc[5] + bb.y, 0.0f);
        float r6 = fmaxf(acc[6] + bb.z, 0.0f);
        float r7 = fmaxf(acc[7] + bb.w, 0.0f);
        __half2 h01 = __floats2half2_rn(r0, r1);
        __half2 h23 = __floats2half2_rn(r2, r3);
        __half2 h45 = __floats2half2_rn(r4, r5);
        __half2 h67 = __floats2half2_rn(r6, r7);
        uint4 pk;
        pk.x = *reinterpret_cast<unsigned*>(&h01);
        pk.y = *reinterpret_cast<unsigned*>(&h23);
        pk.z = *reinterpret_cast<unsigned*>(&h45);
        pk.w = *reinterpret_cast<unsigned*>(&h67);
        ((uint4*)g_Hh)[(long long)w * 16 + sub] = pk;
    }
}

// ======== GEMM2: S2h = Hh @ W2 (32 rows/block, 160 thr, fp16 H input) =========
#define G2_ROWS 32
__global__ void gemm2_kernel(const float* __restrict__ W2, int n) {
    __shared__ float hs[G2_ROWS * D];    // 16 KB (fp32 after convert)
    int base = blockIdx.x * G2_ROWS;
    int tid = threadIdx.x;                // 160
    const uint2* Hv = (const uint2*)g_Hh; // 4 halves per uint2
    for (int i = tid; i < G2_ROWS * 32; i += 160) {
        int r = base + (i >> 5);
        uint2 pk = (r < n) ? Hv[(long long)r * 32 + (i & 31)] : make_uint2(0, 0);
        __half2 h01 = *reinterpret_cast<__half2*>(&pk.x);
        __half2 h23 = *reinterpret_cast<__half2*>(&pk.y);
        float2 f01 = __half22float2(h01);
        float2 f23 = __half22float2(h23);
        float* dst = hs + (i >> 5) * D + (i & 31) * 4;
        dst[0] = f01.x; dst[1] = f01.y; dst[2] = f23.x; dst[3] = f23.y;
    }
    __syncthreads();
    int c = tid % C;
    int rg = tid / C;
    float acc[8];
#pragma unroll
    for (int j = 0; j < 8; j++) acc[j] = 0.0f;
#pragma unroll 4
    for (int k = 0; k < D; k++) {
        float wv = W2[k * C + c];
#pragma unroll
        for (int j = 0; j < 8; j++)
            acc[j] = fmaf(hs[(rg * 8 + j) * D + k], wv, acc[j]);
    }
#pragma unroll
    for (int j = 0; j < 8; j++) {
        int r = base + rg * 8 + j;
        if (r < n) g_S2h[(long long)r * C + c] = __float2half_rn(acc[j]);
    }
}

// ============ SpMM2 (gather fp16, 16 lanes/row, 4-deep MLP) + logsoftmax ======
__device__ __forceinline__ void fma4h(float4& acc, float w, uint2 pk) {
    __half2 h01 = *reinterpret_cast<__half2*>(&pk.x);
    __half2 h23 = *reinterpret_cast<__half2*>(&pk.y);
    float2 f01 = __half22float2(h01);
    float2 f23 = __half22float2(h23);
    acc.x = fmaf(w, f01.x, acc.x); acc.y = fmaf(w, f01.y, acc.y);
    acc.z = fmaf(w, f23.x, acc.z); acc.w = fmaf(w, f23.y, acc.w);
}

__global__ void spmm2_kernel(const float* __restrict__ b2,
                             float* __restrict__ out) {
    int gt = blockIdx.x * blockDim.x + threadIdx.x;
    int r = gt >> 4;
    int lane16 = gt & 15;
    if (r >= NODES) return;
    bool act = lane16 < 10;
    int i = g_rs[r], end = g_rs[r + 1];
    float4 acc = make_float4(0, 0, 0, 0);
    const uint2* S2v = (const uint2*)g_S2h;
    for (; i + 4 <= end; i += 4) {
        unsigned e[4];
#pragma unroll
        for (int j = 0; j < 4; j++) e[j] = g_edge[i + j];
        if (act) {
            uint2 v[4];
#pragma unroll
            for (int j = 0; j < 4; j++)
                v[j] = S2v[(long long)(e[j] & 0xFFFFu) * 10 + lane16];
#pragma unroll
            for (int j = 0; j < 4; j++) fma4h(acc, edge_w(e[j]), v[j]);
        }
    }
    for (; i < end; i++) {
        unsigned e0 = g_edge[i];
        if (act) {
            uint2 v0 = S2v[(long long)(e0 & 0xFFFFu) * 10 + lane16];
            fma4h(acc, edge_w(e0), v0);
        }
    }
    float4 v = make_float4(0, 0, 0, 0);
    if (act) {
        float4 bv = ((const float4*)b2)[lane16];
        v.x = acc.x + bv.x; v.y = acc.y + bv.y;
        v.z = acc.z + bv.z; v.w = acc.w + bv.w;
    }
    float m = act ? fmaxf(fmaxf(v.x, v.y), fmaxf(v.z, v.w)) : -CUDART_INF_F;
#pragma unroll
    for (int off = 8; off > 0; off >>= 1)
        m = fmaxf(m, __shfl_xor_sync(0xffffffffu, m, off, 16));
    float s = act ? (__expf(v.x - m) + __expf(v.y - m) +
                     __expf(v.z - m) + __expf(v.w - m)) : 0.0f;
#pragma unroll
    for (int off = 8; off > 0; off >>= 1)
        s += __shfl_xor_sync(0xffffffffu, s, off, 16);
    float lse = m + __logf(s);
    if (act) {
        float4 o;
        o.x = v.x - lse; o.y = v.y - lse; o.z = v.z - lse; o.w = v.w - lse;
        ((float4*)out)[(long long)r * 10 + lane16] = o;
    }
}

// =============================================================================
extern "C" void kernel_launch(void* const* d_in, const int* in_sizes, int n_in,
                              void* d_out, int out_size) {
    const float* x  = (const float*)d_in[0];
    const int*   ei = (const int*)d_in[1];    // int32
    const float* ew = (const float*)d_in[2];
    const float* W1 = (const float*)d_in[3];
    const float* b1 = (const float*)d_in[4];
    const float* W2 = (const float*)d_in[5];
    const float* b2 = (const float*)d_in[6];
    float* out = (float*)d_out;

    int n = in_sizes[0] / D;      // 50000
    int E = in_sizes[1] / 2;      // 1.6M

    static bool attr_set = false;
    if (!attr_set) {
        cudaFuncSetAttribute(gemm1_kernel,
                             cudaFuncAttributeMaxDynamicSharedMemorySize, G1_SMEM);
        attr_set = true;
    }

    // ---- weight conversion + CSR build (single stream) ----
    convw_kernel<<<(D * D / 2 + 255) / 256, 256>>>(W1);
    int eThreads = (E + 3) / 4;
    hist_kernel<<<(eThreads + 255) / 256, 256>>>(ei, E);
    scanA_kernel<<<SCAN_B, 1024>>>();
    scanC_kernel<<<SCAN_B, 1024>>>();
    scatter_kernel<<<(eThreads + 255) / 256, 256>>>(ei, ew, E);

    // ---- layer 1 ----
    gemm1_kernel<<<(n + 127) / 128, 256, G1_SMEM>>>(x, n);
    {
        long long threads = (long long)n * 32;
        spmm1_kernel<<<(int)((threads + 255) / 256), 256>>>(b1);
    }

    // ---- layer 2 ----
    gemm2_kernel<<<(n + G2_ROWS - 1) / G2_ROWS, 160>>>(W2, n);
    {
        long long threads = (long long)n * 16;
        spmm2_kernel<<<(int)((threads + 255) / 256), 256>>>(b2, out);
    }
}

// round 16
// speedup vs baseline: 1.7471x; 1.1668x over previous
#include <cuda_runtime.h>
#include <cuda_fp16.h>
#include <mma.h>
#include <cstdint>
#include <math_constants.h>

using namespace nvcuda;

#define NODES 50000
#define D 128
#define C 40
#define CPAD 64
#define EDGES_MAX 1600000
#define SCAN_B 49          // 49 * 1024 = 50176 >= NODES
#define SCAN_PAD 50176
#define XPAD 136           // half ldm padding (272B row stride, conflict-free LDSM)
#define FPAD 68            // float ldm for warp-private epilogue buffer
#define WPAD 72            // half ldm for W2 tile (144B stride, conflict-free)
#define XH_BYTES (128 * XPAD * 2)          // 34816
#define G1_SMEM  (XH_BYTES * 2)            // 69632
#define G2_SMEM  (XH_BYTES + 128 * WPAD * 2)  // 34816 + 18432 = 53248

// ---------------- scratch (__device__ globals; no allocations) ----------------
__device__ __half  g_W1h[D * D];         // fp16 W1 (converted once per call)
__device__ __half  g_W2h[D * CPAD];      // fp16 W2 padded to 64 cols
__device__ __half  g_S1h[NODES * D];     // x @ W1   (fp16 storage)
__device__ __half  g_Hh [NODES * D];     // relu(agg + b1)  (fp16 storage)
__device__ __half  g_S2h[NODES * C];     // H @ W2   (fp16 storage)
__device__ int     g_cnt[SCAN_PAD];      // zero at load; scanC re-zeros
__device__ int     g_scanA[SCAN_PAD];
__device__ int     g_bsum[64];
__device__ int     g_rs[NODES + 1];
__device__ int     g_cur[NODES];
__device__ unsigned g_edge[EDGES_MAX];   // packed {w:fp16 <<16 | col:u16}, CSR order

// ========== W1 + W2 fp32 -> fp16 (once per call; W2 padded to 64) =============
__global__ void convw_kernel(const float* __restrict__ W1,
                             const float* __restrict__ W2) {
    int i = blockIdx.x * blockDim.x + threadIdx.x;
    if (i < D * D / 2) {                      // W1: half2 units
        float2 v = ((const float2*)W1)[i];
        ((__half2*)g_W1h)[i] = __floats2half2_rn(v.x, v.y);
    }
    if (i < D * CPAD) {                       // W2: scalar halves (padded)
        int r = i >> 6, c = i & 63;
        g_W2h[i] = (c < C) ? __float2half_rn(W2[r * C + c]) : __half(0.0f);
    }
}

// ================= CSR build =================
__global__ void hist_kernel(const int* __restrict__ ei, int E) {
    int t = blockIdx.x * blockDim.x + threadIdx.x;
    int base = t * 4;
    if (base >= E) return;
    if (base + 4 <= E && (E & 3) == 0) {
        int4 r4 = *(const int4*)(ei + base);
        atomicAdd(&g_cnt[r4.x], 1);
        atomicAdd(&g_cnt[r4.y], 1);
        atomicAdd(&g_cnt[r4.z], 1);
        atomicAdd(&g_cnt[r4.w], 1);
    } else {
        for (int j = base; j < E && j < base + 4; j++)
            atomicAdd(&g_cnt[ei[j]], 1);
    }
}

// warp-shuffle inclusive scan (2 block syncs total)
__global__ void scanA_kernel() {
    int t = threadIdx.x;
    int i = blockIdx.x * 1024 + t;
    int lane = t & 31, warp = t >> 5;
    int v = g_cnt[i];
#pragma unroll
    for (int off = 1; off < 32; off <<= 1) {
        int u = __shfl_up_sync(0xffffffffu, v, off);
        if (lane >= off) v += u;
    }
    __shared__ int wsum[32];
    if (lane == 31) wsum[warp] = v;
    __syncthreads();
    if (warp == 0) {
        int s = wsum[lane];
#pragma unroll
        for (int off = 1; off < 32; off <<= 1) {
            int u = __shfl_up_sync(0xffffffffu, s, off);
            if (lane >= off) s += u;
        }
        wsum[lane] = s;
    }
    __syncthreads();
    int incl = v + (warp ? wsum[warp - 1] : 0);
    g_scanA[i] = incl;
    if (t == 1023) g_bsum[blockIdx.x] = incl;
}

__global__ void scanC_kernel() {
    __shared__ int s_off;
    __shared__ int warp_s[2];
    int t = threadIdx.x;
    if (t < 64) {
        int v = (t < (int)blockIdx.x) ? g_bsum[t] : 0;
#pragma unroll
        for (int off = 16; off > 0; off >>= 1)
            v += __shfl_down_sync(0xffffffffu, v, off);
        if ((t & 31) == 0) warp_s[t >> 5] = v;
    }
    __syncthreads();
    if (t == 0) s_off = warp_s[0] + warp_s[1];
    __syncthreads();
    int i = blockIdx.x * 1024 + t;
    int incl = g_scanA[i] + s_off;
    int cnt = g_cnt[i];
    g_cnt[i] = 0;                       // reset for next graph replay
    if (i < NODES) {
        int ex = incl - cnt;
        g_rs[i]  = ex;
        g_cur[i] = ex;
        if (i == NODES - 1) g_rs[NODES] = incl;
    }
}

__device__ __forceinline__ unsigned pack_edge(int col, float w) {
    unsigned hw = __half_as_ushort(__float2half_rn(w));
    return (unsigned)col | (hw << 16);
}

__global__ void scatter_kernel(const int* __restrict__ ei,
                               const float* __restrict__ ew, int E) {
    int t = blockIdx.x * blockDim.x + threadIdx.x;
    int base = t * 4;
    if (base >= E) return;
    if (base + 4 <= E && (E & 3) == 0) {
        int4   r4 = *(const int4*)(ei + base);
        int4   c4 = *(const int4*)(ei + E + base);
        float4 w4 = *(const float4*)(ew + base);
        int p0 = atomicAdd(&g_cur[r4.x], 1);
        int p1 = atomicAdd(&g_cur[r4.y], 1);
        int p2 = atomicAdd(&g_cur[r4.z], 1);
        int p3 = atomicAdd(&g_cur[r4.w], 1);
        g_edge[p0] = pack_edge(c4.x, w4.x);
        g_edge[p1] = pack_edge(c4.y, w4.y);
        g_edge[p2] = pack_edge(c4.z, w4.z);
        g_edge[p3] = pack_edge(c4.w, w4.w);
    } else {
        for (int j = base; j < E && j < base + 4; j++) {
            int p = atomicAdd(&g_cur[ei[j]], 1);
            g_edge[p] = pack_edge(ei[E + j], ew[j]);
        }
    }
}

// ====== GEMM1 (wmma): padded smem for BOTH operands, 128 rows/block ===========
__global__ void gemm1_kernel(const float* __restrict__ x, int n) {
    extern __shared__ __align__(16) char smem_raw[];
    __half* xh = (__half*)smem_raw;                  // 128 x XPAD halves
    __half* wh = (__half*)(smem_raw + XH_BYTES);     // 128 x XPAD halves

    int base = blockIdx.x * 128;
    int tid = threadIdx.x;
    int wid = tid >> 5;
    int lane = tid & 31;

    {
        const uint4* Wv = (const uint4*)g_W1h;
        for (int i = tid; i < 128 * 16; i += 256) {
            int rr = i >> 4, cc = i & 15;
            *(uint4*)(wh + rr * XPAD + cc * 8) = Wv[i];
        }
    }
    {
        const float4* xv = (const float4*)x;
        for (int i = tid; i < 128 * 32; i += 256) {
            int rr = i >> 5, cc = i & 31;
            int r = base + rr;
            float4 v = (r < n) ? xv[(long long)r * 32 + cc] : make_float4(0, 0, 0, 0);
            __half2 h01 = __floats2half2_rn(v.x, v.y);
            __half2 h23 = __floats2half2_rn(v.z, v.w);
            uint2 pk;
            pk.x = *reinterpret_cast<unsigned*>(&h01);
            pk.y = *reinterpret_cast<unsigned*>(&h23);
            *(uint2*)(xh + rr * XPAD + cc * 4) = pk;
        }
    }
    __syncthreads();

    wmma::fragment<wmma::accumulator, 16, 16, 16, float> acc[8];
#pragma unroll
    for (int c = 0; c < 8; c++) wmma::fill_fragment(acc[c], 0.0f);
#pragma unroll
    for (int k = 0; k < 8; k++) {
        wmma::fragment<wmma::matrix_a, 16, 16, 16, __half, wmma::row_major> a;
        wmma::load_matrix_sync(a, xh + (wid * 16) * XPAD + k * 16, XPAD);
#pragma unroll
        for (int c = 0; c < 8; c++) {
            wmma::fragment<wmma::matrix_b, 16, 16, 16, __half, wmma::row_major> b;
            wmma::load_matrix_sync(b, wh + (k * 16) * XPAD + c * 16, XPAD);
            wmma::mma_sync(acc[c], a, b, acc[c]);
        }
    }
    float* fbuf = (float*)(xh + (wid * 16) * XPAD);
    __syncwarp();
#pragma unroll
    for (int h = 0; h < 2; h++) {
#pragma unroll
        for (int c = 0; c < 4; c++)
            wmma::store_matrix_sync(fbuf + c * 16, acc[h * 4 + c],
                                    FPAD, wmma::mem_row_major);
        __syncwarp();
        int row16 = lane >> 1;
        int sub   = lane & 1;
        int r = base + wid * 16 + row16;
        if (r < n) {
            const float* src = fbuf + row16 * FPAD + sub * 32;
            uint2* dst = (uint2*)(g_S1h + (long long)r * D + h * 64 + sub * 32);
#pragma unroll
            for (int j = 0; j < 8; j++) {
                float4 v = *(const float4*)(src + j * 4);
                __half2 h01 = __floats2half2_rn(v.x, v.y);
                __half2 h23 = __floats2half2_rn(v.z, v.w);
                uint2 pk;
                pk.x = *reinterpret_cast<unsigned*>(&h01);
                pk.y = *reinterpret_cast<unsigned*>(&h23);
                dst[j] = pk;
            }
        }
        __syncwarp();
    }
}

// ===== SpMM1: 2 edges per gather instr (uint4/lane), warp/row =================
__device__ __forceinline__ float edge_w(unsigned e) {
    return __half2float(__ushort_as_half((unsigned short)(e >> 16)));
}

__device__ __forceinline__ void fma8h(float* acc, float w, uint4 pk) {
    __half2 h01 = *reinterpret_cast<__half2*>(&pk.x);
    __half2 h23 = *reinterpret_cast<__half2*>(&pk.y);
    __half2 h45 = *reinterpret_cast<__half2*>(&pk.z);
    __half2 h67 = *reinterpret_cast<__half2*>(&pk.w);
    float2 f01 = __half22float2(h01);
    float2 f23 = __half22float2(h23);
    float2 f45 = __half22float2(h45);
    float2 f67 = __half22float2(h67);
    acc[0] = fmaf(w, f01.x, acc[0]); acc[1] = fmaf(w, f01.y, acc[1]);
    acc[2] = fmaf(w, f23.x, acc[2]); acc[3] = fmaf(w, f23.y, acc[3]);
    acc[4] = fmaf(w, f45.x, acc[4]); acc[5] = fmaf(w, f45.y, acc[5]);
    acc[6] = fmaf(w, f67.x, acc[6]); acc[7] = fmaf(w, f67.y, acc[7]);
}

__global__ void spmm1_kernel(const float* __restrict__ b1) {
    int w = (blockIdx.x * blockDim.x + threadIdx.x) >> 5;
    int lane = threadIdx.x & 31;
    if (w >= NODES) return;
    int pair = lane >> 4;
    int sub  = lane & 15;
    int i = g_rs[w], end = g_rs[w + 1];
    float acc[8];
#pragma unroll
    for (int k = 0; k < 8; k++) acc[k] = 0.0f;
    const uint4* S1v = (const uint4*)g_S1h;

    for (; i + 8 <= end; i += 8) {
        unsigned e[4];
#pragma unroll
        for (int j = 0; j < 4; j++) e[j] = g_edge[i + 2 * j + pair];
        uint4 v[4];
#pragma unroll
        for (int j = 0; j < 4; j++)
            v[j] = S1v[(long long)(e[j] & 0xFFFFu) * 16 + sub];
#pragma unroll
        for (int j = 0; j < 4; j++) fma8h(acc, edge_w(e[j]), v[j]);
    }
    for (; i < end; i += 2) {
        int idx = i + pair;
        if (idx < end) {
            unsigned e0 = g_edge[idx];
            uint4 v0 = S1v[(long long)(e0 & 0xFFFFu) * 16 + sub];
            fma8h(acc, edge_w(e0), v0);
        }
    }
#pragma unroll
    for (int k = 0; k < 8; k++)
        acc[k] += __shfl_down_sync(0xffffffffu, acc[k], 16);

    if (pair == 0) {
        const float4* b1v = (const float4*)b1;
        float4 ba = b1v[sub * 2];
        float4 bb = b1v[sub * 2 + 1];
        float r0 = fmaxf(acc[0] + ba.x, 0.0f);
        float r1 = fmaxf(acc[1] + ba.y, 0.0f);
        float r2 = fmaxf(acc[2] + ba.z, 0.0f);
        float r3 = fmaxf(acc[3] + ba.w, 0.0f);
        float r4 = fmaxf(acc[4] + bb.x, 0.0f);
        float r5 = fmaxf(acc[5] + bb.y, 0.0f);
        float r6 = fmaxf(acc[6] + bb.z, 0.0f);
        float r7 = fmaxf(acc[7] + bb.w, 0.0f);
        __half2 h01 = __floats2half2_rn(r0, r1);
        __half2 h23 = __floats2half2_rn(r2, r3);
        __half2 h45 = __floats2half2_rn(r4, r5);
        __half2 h67 = __floats2half2_rn(r6, r7);
        uint4 pk;
        pk.x = *reinterpret_cast<unsigned*>(&h01);
        pk.y = *reinterpret_cast<unsigned*>(&h23);
        pk.z = *reinterpret_cast<unsigned*>(&h45);
        pk.w = *reinterpret_cast<unsigned*>(&h67);
        ((uint4*)g_Hh)[(long long)w * 16 + sub] = pk;
    }
}

// ======= GEMM2 (wmma): Hh(fp16) @ W2h, 128 rows/block, proven template ========
__global__ void gemm2_kernel(int n) {
    extern __shared__ __align__(16) char smem_raw[];
    __half* Hs  = (__half*)smem_raw;                 // 128 x XPAD halves
    __half* w2s = (__half*)(smem_raw + XH_BYTES);    // 128 x WPAD halves

    int base = blockIdx.x * 128;
    int tid = threadIdx.x;
    int wid = tid >> 5;
    int lane = tid & 31;

    // stage W2h (128x64 halves -> padded WPAD rows)
    {
        const uint4* Wv = (const uint4*)g_W2h;       // 128 x 8 uint4
        for (int i = tid; i < 128 * 8; i += 256) {
            int rr = i >> 3, cc = i & 7;
            *(uint4*)(w2s + rr * WPAD + cc * 8) = Wv[i];
        }
    }
    // stage Hh tile (fp16 already, no conversion)
    {
        const uint4* Hv = (const uint4*)g_Hh;        // row = 16 uint4
        for (int i = tid; i < 128 * 16; i += 256) {
            int rr = i >> 4, cc = i & 15;
            int r = base + rr;
            uint4 v = (r < n) ? Hv[(long long)r * 16 + cc] : make_uint4(0, 0, 0, 0);
            *(uint4*)(Hs + rr * XPAD + cc * 8) = v;
        }
    }
    __syncthreads();

    // each warp: rows wid*16..+15, cols 0..63 (4 frags)
    wmma::fragment<wmma::accumulator, 16, 16, 16, float> acc[4];
#pragma unroll
    for (int c = 0; c < 4; c++) wmma::fill_fragment(acc[c], 0.0f);
#pragma unroll
    for (int k = 0; k < 8; k++) {
        wmma::fragment<wmma::matrix_a, 16, 16, 16, __half, wmma::row_major> a;
        wmma::load_matrix_sync(a, Hs + (wid * 16) * XPAD + k * 16, XPAD);
#pragma unroll
        for (int c = 0; c < 4; c++) {
            wmma::fragment<wmma::matrix_b, 16, 16, 16, __half, wmma::row_major> b;
            wmma::load_matrix_sync(b, w2s + (k * 16) * WPAD + c * 16, WPAD);
            wmma::mma_sync(acc[c], a, b, acc[c]);
        }
    }
    // epilogue: warp-private reuse of this warp's own 16-row Hs slice
    float* fbuf = (float*)(Hs + (wid * 16) * XPAD);  // 16 x FPAD floats fits
    __syncwarp();
#pragma unroll
    for (int c = 0; c < 4; c++)
        wmma::store_matrix_sync(fbuf + c * 16, acc[c], FPAD, wmma::mem_row_major);
    __syncwarp();
    // write 16 rows x 40 cols (5 uint4 per row) = 80 uint4
    for (int idx = lane; idx < 80; idx += 32) {
        int row16 = idx / 5, chunk = idx % 5;
        int r = base + wid * 16 + row16;
        if (r < n) {
            const float* src = fbuf + row16 * FPAD + chunk * 8;
            __half2 h01 = __floats2half2_rn(src[0], src[1]);
            __half2 h23 = __floats2half2_rn(src[2], src[3]);
            __half2 h45 = __floats2half2_rn(src[4], src[5]);
            __half2 h67 = __floats2half2_rn(src[6], src[7]);
            uint4 pk;
            pk.x = *reinterpret_cast<unsigned*>(&h01);
            pk.y = *reinterpret_cast<unsigned*>(&h23);
            pk.z = *reinterpret_cast<unsigned*>(&h45);
            pk.w = *reinterpret_cast<unsigned*>(&h67);
            *(uint4*)(g_S2h + (long long)r * C + chunk * 8) = pk;
        }
    }
}

// ===== SpMM2 v2: warp/row, 2 edges per gather instr + b2 + log_softmax ========
__device__ __forceinline__ void fma4h(float4& acc, float w, uint2 pk) {
    __half2 h01 = *reinterpret_cast<__half2*>(&pk.x);
    __half2 h23 = *reinterpret_cast<__half2*>(&pk.y);
    float2 f01 = __half22float2(h01);
    float2 f23 = __half22float2(h23);
    acc.x = fmaf(w, f01.x, acc.x); acc.y = fmaf(w, f01.y, acc.y);
    acc.z = fmaf(w, f23.x, acc.z); acc.w = fmaf(w, f23.y, acc.w);
}

__global__ void spmm2_kernel(const float* __restrict__ b2,
                             float* __restrict__ out) {
    int r = (blockIdx.x * blockDim.x + threadIdx.x) >> 5;
    int lane = threadIdx.x & 31;
    if (r >= NODES) return;
    int pair = lane >> 4;
    int sub  = lane & 15;
    bool act = sub < 10;
    int i = g_rs[r], end = g_rs[r + 1];
    float4 acc = make_float4(0, 0, 0, 0);
    const uint2* S2v = (const uint2*)g_S2h;   // row = 10 uint2
    for (; i + 8 <= end; i += 8) {
        unsigned e[4];
#pragma unroll
        for (int j = 0; j < 4; j++) e[j] = g_edge[i + 2 * j + pair];
        if (act) {
            uint2 v[4];
#pragma unroll
            for (int j = 0; j < 4; j++)
                v[j] = S2v[(long long)(e[j] & 0xFFFFu) * 10 + sub];
#pragma unroll
            for (int j = 0; j < 4; j++) fma4h(acc, edge_w(e[j]), v[j]);
        }
    }
    for (; i < end; i += 2) {
        int idx = i + pair;
        if (idx < end) {
            unsigned e0 = g_edge[idx];
            if (act) {
                uint2 v0 = S2v[(long long)(e0 & 0xFFFFu) * 10 + sub];
                fma4h(acc, edge_w(e0), v0);
            }
        }
    }
    // combine pairs
    acc.x += __shfl_down_sync(0xffffffffu, acc.x, 16);
    acc.y += __shfl_down_sync(0xffffffffu, acc.y, 16);
    acc.z += __shfl_down_sync(0xffffffffu, acc.z, 16);
    acc.w += __shfl_down_sync(0xffffffffu, acc.w, 16);

    // log_softmax among lanes 0..9 (pair-0 half)
    float4 v = make_float4(0, 0, 0, 0);
    bool lead = (pair == 0) && act;
    if (lead) {
        float4 bv = ((const float4*)b2)[sub];
        v.x = acc.x + bv.x; v.y = acc.y + bv.y;
        v.z = acc.z + bv.z; v.w = acc.w + bv.w;
    }
    float m = lead ? fmaxf(fmaxf(v.x, v.y), fmaxf(v.z, v.w)) : -CUDART_INF_F;
#pragma unroll
    for (int off = 8; off > 0; off >>= 1)
        m = fmaxf(m, __shfl_xor_sync(0xffffffffu, m, off, 16));
    float s = lead ? (__expf(v.x - m) + __expf(v.y - m) +
                      __expf(v.z - m) + __expf(v.w - m)) : 0.0f;
#pragma unroll
    for (int off = 8; off > 0; off >>= 1)
        s += __shfl_xor_sync(0xffffffffu, s, off, 16);
    float lse = m + __logf(s);
    if (lead) {
        float4 o;
        o.x = v.x - lse; o.y = v.y - lse; o.z = v.z - lse; o.w = v.w - lse;
        ((float4*)out)[(long long)r * 10 + sub] = o;
    }
}

// =============================================================================
extern "C" void kernel_launch(void* const* d_in, const int* in_sizes, int n_in,
                              void* d_out, int out_size) {
    const float* x  = (const float*)d_in[0];
    const int*   ei = (const int*)d_in[1];    // int32
    const float* ew = (const float*)d_in[2];
    const float* W1 = (const float*)d_in[3];
    const float* b1 = (const float*)d_in[4];
    const float* W2 = (const float*)d_in[5];
    const float* b2 = (const float*)d_in[6];
    float* out = (float*)d_out;

    int n = in_sizes[0] / D;      // 50000
    int E = in_sizes[1] / 2;      // 1.6M

    static bool attr_set = false;
    if (!attr_set) {
        cudaFuncSetAttribute(gemm1_kernel,
                             cudaFuncAttributeMaxDynamicSharedMemorySize, G1_SMEM);
        cudaFuncSetAttribute(gemm2_kernel,
                             cudaFuncAttributeMaxDynamicSharedMemorySize, G2_SMEM);
        attr_set = true;
    }

    // ---- weight conversion + CSR build ----
    convw_kernel<<<(D * CPAD + 255) / 256, 256>>>(W1, W2);
    int eThreads = (E + 3) / 4;
    hist_kernel<<<(eThreads + 255) / 256, 256>>>(ei, E);
    scanA_kernel<<<SCAN_B, 1024>>>();
    scanC_kernel<<<SCAN_B, 1024>>>();
    scatter_kernel<<<(eThreads + 255) / 256, 256>>>(ei, ew, E);

    // ---- layer 1 ----
    gemm1_kernel<<<(n + 127) / 128, 256, G1_SMEM>>>(x, n);
    {
        long long threads = (long long)n * 32;
        spmm1_kernel<<<(int)((threads + 255) / 256), 256>>>(b1);
    }

    // ---- layer 2 ----
    gemm2_kernel<<<(n + 127) / 128, 256, G2_SMEM>>>(n);
    {
        long long threads = (long long)n * 32;
        spmm2_kernel<<<(int)((threads + 255) / 256), 256>>>(b2, out);
    }
}